// round 1
// baseline (speedup 1.0000x reference)
#include <cuda_runtime.h>
#include <math.h>

#define TT 16
#define CCH 64
#define HHH 48
#define WWI 48
#define HWSZ 2304
#define THWSZ 36864
#define WW2 24
#define SS 576
#define RCC 4

// ---------------- scratch (device globals; no allocations) ----------------
static __device__ float g_x2[CCH * THWSZ];            // [c][t][h][w]
static __device__ float g_off[2 * TT * 2 * SS];       // [branch][t][o][s]
static __device__ float g_part_cs[2][TT * CCH * SS];  // [branch][t][c][s]
static __device__ float g_part_sc[2][TT * SS * CCH];  // [branch][t][s][c]
static __device__ float g_aff[TT * SS * HWSZ];        // [t][s][hw] (reused per branch)
static __device__ float g_mean[TT * HWSZ];
static __device__ float g_maxv[TT * HWSZ];
static __device__ float g_varv[TT * HWSZ];
static __device__ float g_yv[TT * HWSZ];
static __device__ float g_feat[TT * HWSZ * CCH];      // [t][hw][c]
static __device__ float g_xd[RCC * THWSZ];
static __device__ float g_agg[RCC * THWSZ];

__device__ __forceinline__ float sigm(float v) { return 1.0f / (1.0f + __expf(-v)); }

// ---------------- x2 = w_dc2 @ x  (64x64 channel GEMM over 36864 positions) --
__global__ void k_x2(const float* __restrict__ x, const float* __restrict__ w) {
    __shared__ float Ws[64][64];  // Ws[c][o]  (transposed weight)
    __shared__ float Xs[64][64];  // Xs[c][pos]
    int tid = threadIdx.x;
    int pos0 = blockIdx.x * 64;
    for (int i = tid; i < 4096; i += 256) {
        int o = i >> 6, c = i & 63;
        Ws[c][o] = w[i];
    }
    int lr = tid >> 4, lc4 = (tid & 15) * 4;
#pragma unroll
    for (int v = 0; v < 4; v++) {
        int c = lr + v * 16;
        *(float4*)&Xs[c][lc4] = *(const float4*)&x[c * THWSZ + pos0 + lc4];
    }
    __syncthreads();
    int ty = tid >> 4, tx = tid & 15;
    float acc[4][4] = {};
#pragma unroll
    for (int k = 0; k < 64; k++) {
        float4 a = *(float4*)&Ws[k][ty * 4];
        float4 b = *(float4*)&Xs[k][tx * 4];
        float av[4] = {a.x, a.y, a.z, a.w};
        float bv[4] = {b.x, b.y, b.z, b.w};
#pragma unroll
        for (int i = 0; i < 4; i++)
#pragma unroll
            for (int j = 0; j < 4; j++) acc[i][j] = fmaf(av[i], bv[j], acc[i][j]);
    }
#pragma unroll
    for (int i = 0; i < 4; i++) {
        float4 o4 = make_float4(acc[i][0], acc[i][1], acc[i][2], acc[i][3]);
        *(float4*)&g_x2[(ty * 4 + i) * THWSZ + pos0 + tx * 4] = o4;
    }
}

// ---------------- offset convs: stride-2 3x3 over (x + shifted x2) ----------
__global__ void k_off(const float* __restrict__ x,
                      const float* __restrict__ wl, const float* __restrict__ bl,
                      const float* __restrict__ wr, const float* __restrict__ br_) {
    int idx = blockIdx.x * blockDim.x + threadIdx.x;
    if (idx >= 2 * TT * 2 * SS) return;
    int branch = idx / (TT * 2 * SS);
    int r = idx % (TT * 2 * SS);
    int t = r / (2 * SS);
    int o = (r / SS) & 1;
    int s = r % SS;
    int i = s / WW2, j = s % WW2;
    int tsrc = (branch == 0) ? min(t + 1, TT - 1) : max(t - 1, 0);
    const float* wofs = (branch == 0) ? wl : wr;
    float acc = (branch == 0) ? bl[o] : br_[o];
    for (int c = 0; c < CCH; c++) {
        const float* xp = x + c * THWSZ + t * HWSZ;
        const float* x2p = g_x2 + c * THWSZ + tsrc * HWSZ;
        const float* wp = wofs + (o * CCH + c) * 9;
#pragma unroll
        for (int ki = 0; ki < 3; ki++) {
            int h = 2 * i - 1 + ki;
            if (h < 0 || h >= HHH) continue;
#pragma unroll
            for (int kj = 0; kj < 3; kj++) {
                int w = 2 * j - 1 + kj;
                if (w < 0 || w >= WWI) continue;
                acc = fmaf(xp[h * WWI + w] + x2p[h * WWI + w], wp[ki * 3 + kj], acc);
            }
        }
    }
    g_off[idx] = acc;
}

// ---------------- bilinear grid-sample of shifted x2 ------------------------
__global__ void k_sample() {
    int idx = blockIdx.x * blockDim.x + threadIdx.x;
    if (idx >= 2 * TT * SS) return;
    int branch = idx / (TT * SS);
    int t = (idx % (TT * SS)) / SS;
    int s = idx % SS;
    int i = s / WW2, j = s % WW2;
    float off0 = g_off[((branch * TT + t) * 2 + 0) * SS + s];
    float off1 = g_off[((branch * TT + t) * 2 + 1) * SS + s];
    float v0 = 2.0f * (float)j + off0;
    float v1 = 2.0f * (float)i + off1;
    float gh = 2.0f * v0 / 23.0f - 1.0f;   // becomes sample x
    float gw = 2.0f * v1 / 23.0f - 1.0f;   // becomes sample y
    float xs = ((gh + 1.0f) * 48.0f - 1.0f) * 0.5f;
    float ys = ((gw + 1.0f) * 48.0f - 1.0f) * 0.5f;
    float x0f = floorf(xs), y0f = floorf(ys);
    int x0 = (int)x0f, y0 = (int)y0f;
    float fx = xs - x0f, fy = ys - y0f;
    float wgt[4] = {(1.0f - fx) * (1.0f - fy), fx * (1.0f - fy),
                    (1.0f - fx) * fy, fx * fy};
    int xi[4] = {x0, x0 + 1, x0, x0 + 1};
    int yi[4] = {y0, y0, y0 + 1, y0 + 1};
    float wv[4];
    int id[4];
#pragma unroll
    for (int k = 0; k < 4; k++) {
        bool valid = (xi[k] >= 0) && (xi[k] < WWI) && (yi[k] >= 0) && (yi[k] < HHH);
        wv[k] = valid ? wgt[k] : 0.0f;
        int cy = min(max(yi[k], 0), HHH - 1);
        int cx = min(max(xi[k], 0), WWI - 1);
        id[k] = cy * WWI + cx;
    }
    int tsrc = (branch == 0) ? min(t + 1, TT - 1) : max(t - 1, 0);
    for (int c = 0; c < CCH; c++) {
        const float* img = g_x2 + c * THWSZ + tsrc * HWSZ;
        float val = wv[0] * img[id[0]] + wv[1] * img[id[1]] +
                    wv[2] * img[id[2]] + wv[3] * img[id[3]];
        g_part_cs[branch][(t * CCH + c) * SS + s] = val;
        g_part_sc[branch][(t * SS + s) * CCH + c] = val;
    }
}

// ---------------- GEMM1: Aff[t][s][hw] = sum_c part[c][s] * x[c][hw] --------
__global__ void k_gemm1(const float* __restrict__ x, int branch) {
    __shared__ float Xs[64][64];  // [c][hw]
    __shared__ float Ps[64][64];  // [c][s]
    int t = blockIdx.z;
    int hw0 = blockIdx.x * 64, s0 = blockIdx.y * 64;
    const float* P = g_part_cs[branch];
    int tid = threadIdx.x;
    int lr = tid >> 4, lc4 = (tid & 15) * 4;
#pragma unroll
    for (int v = 0; v < 4; v++) {
        int c = lr + v * 16;
        *(float4*)&Xs[c][lc4] = *(const float4*)&x[c * THWSZ + t * HWSZ + hw0 + lc4];
        *(float4*)&Ps[c][lc4] = *(const float4*)&P[(t * CCH + c) * SS + s0 + lc4];
    }
    __syncthreads();
    int ty = tid >> 4, tx = tid & 15;
    float acc[4][4] = {};
#pragma unroll
    for (int k = 0; k < 64; k++) {
        float4 a = *(float4*)&Ps[k][ty * 4];  // s rows
        float4 b = *(float4*)&Xs[k][tx * 4];  // hw cols
        float av[4] = {a.x, a.y, a.z, a.w};
        float bv[4] = {b.x, b.y, b.z, b.w};
#pragma unroll
        for (int i = 0; i < 4; i++)
#pragma unroll
            for (int j = 0; j < 4; j++) acc[i][j] = fmaf(av[i], bv[j], acc[i][j]);
    }
#pragma unroll
    for (int i = 0; i < 4; i++) {
        float4 o4 = make_float4(acc[i][0], acc[i][1], acc[i][2], acc[i][3]);
        *(float4*)&g_aff[(t * SS + s0 + ty * 4 + i) * HWSZ + hw0 + tx * 4] = o4;
    }
}

// ---------------- per-pixel stats over s (mean / max / unbiased var) --------
__global__ void k_stats() {
    int t = blockIdx.y;
    int hw = blockIdx.x * 256 + threadIdx.x;
    const float* base = g_aff + t * SS * HWSZ + hw;
    float sum = 0.0f, sq = 0.0f, mx = -3.4e38f;
    for (int s = 0; s < SS; s++) {
        float v = base[s * HWSZ];
        sum += v;
        sq = fmaf(v, v, sq);
        mx = fmaxf(mx, v);
    }
    float mean = sum / 576.0f;
    float var = (sq - sum * sum / 576.0f) / 575.0f;
    g_mean[t * HWSZ + hw] = mean;
    g_maxv[t * HWSZ + hw] = mx;
    g_varv[t * HWSZ + hw] = var;
}

// ---------------- attention gate: y = sigmoid(conv3x3([avg,mx]) + conv3x3(var))
__global__ void k_y(const float* __restrict__ w1, const float* __restrict__ w2) {
    int idx = blockIdx.x * 256 + threadIdx.x;
    if (idx >= TT * HWSZ) return;
    int t = idx / HWSZ;
    int hw = idx % HWSZ;
    int h = hw / WWI, w = hw % WWI;
    float acc = 0.0f;
#pragma unroll
    for (int dh = 0; dh < 3; dh++) {
        int hh = h + dh - 1;
        if (hh < 0 || hh >= HHH) continue;
#pragma unroll
        for (int dw = 0; dw < 3; dw++) {
            int ww = w + dw - 1;
            if (ww < 0 || ww >= WWI) continue;
            int p = t * HWSZ + hh * WWI + ww;
            acc = fmaf(w1[(0 * 3 + dh) * 3 + dw], g_mean[p], acc);
            acc = fmaf(w1[(3 + dh) * 3 + dw], g_maxv[p], acc);
            acc = fmaf(w2[dh * 3 + dw], g_varv[p], acc);
        }
    }
    g_yv[idx] = sigm(acc);
}

// ---------------- GEMM2: feat[t][hw][c] (+)= wscale * sum_s G[hw][s]*P[s][c] -
__global__ void k_gemm2(int branch, const float* __restrict__ w2s, int accum) {
    __shared__ float Gs[64][64];  // [s][hw]
    __shared__ float Bs[64][64];  // [s][c]
    int t = blockIdx.z;
    int hw0 = blockIdx.x * 64;
    const float* Psc = g_part_sc[branch];
    float wscale = w2s[branch];
    int tid = threadIdx.x;
    int lr = tid >> 4, lc4 = (tid & 15) * 4;
    int ty = tid >> 4, tx = tid & 15;
    float acc[4][4] = {};
    for (int k0 = 0; k0 < SS; k0 += 64) {
        __syncthreads();
#pragma unroll
        for (int v = 0; v < 4; v++) {
            int kk = lr + v * 16;
            float4 a = *(const float4*)&g_aff[(t * SS + k0 + kk) * HWSZ + hw0 + lc4];
            float4 yv = *(const float4*)&g_yv[t * HWSZ + hw0 + lc4];
            float4 g;
            g.x = sigm(yv.x * a.x) - 0.5f;
            g.y = sigm(yv.y * a.y) - 0.5f;
            g.z = sigm(yv.z * a.z) - 0.5f;
            g.w = sigm(yv.w * a.w) - 0.5f;
            *(float4*)&Gs[kk][lc4] = g;
            *(float4*)&Bs[kk][lc4] = *(const float4*)&Psc[(t * SS + k0 + kk) * CCH + lc4];
        }
        __syncthreads();
#pragma unroll
        for (int k = 0; k < 64; k++) {
            float4 a = *(float4*)&Gs[k][ty * 4];  // hw rows
            float4 b = *(float4*)&Bs[k][tx * 4];  // c cols
            float av[4] = {a.x, a.y, a.z, a.w};
            float bv[4] = {b.x, b.y, b.z, b.w};
#pragma unroll
            for (int i = 0; i < 4; i++)
#pragma unroll
                for (int j = 0; j < 4; j++) acc[i][j] = fmaf(av[i], bv[j], acc[i][j]);
        }
    }
#pragma unroll
    for (int i = 0; i < 4; i++) {
        float* dst = &g_feat[(t * HWSZ + hw0 + ty * 4 + i) * CCH + tx * 4];
        float4 o4 = make_float4(wscale * acc[i][0], wscale * acc[i][1],
                                wscale * acc[i][2], wscale * acc[i][3]);
        if (accum) {
            float4 p = *(float4*)dst;
            o4.x += p.x; o4.y += p.y; o4.z += p.z; o4.w += p.w;
        }
        *(float4*)dst = o4;
    }
}

// ---------------- xd = w_down @ x -------------------------------------------
__global__ void k_xd(const float* __restrict__ x, const float* __restrict__ wd) {
    int idx = blockIdx.x * blockDim.x + threadIdx.x;
    if (idx >= RCC * THWSZ) return;
    int r = idx / THWSZ, pos = idx % THWSZ;
    float acc = 0.0f;
    for (int c = 0; c < CCH; c++) acc = fmaf(wd[r * CCH + c], x[c * THWSZ + pos], acc);
    g_xd[idx] = acc;
}

// ---------------- 3x depthwise 3D convs, weighted sum -----------------------
__global__ void k_agg(const float* __restrict__ w1, const float* __restrict__ b1,
                      const float* __restrict__ w2, const float* __restrict__ b2,
                      const float* __restrict__ w3, const float* __restrict__ b3,
                      const float* __restrict__ wts) {
    int idx = blockIdx.x * blockDim.x + threadIdx.x;
    if (idx >= RCC * THWSZ) return;
    int r = idx / THWSZ;
    int rem = idx % THWSZ;
    int t = rem / HWSZ;
    int hw = rem % HWSZ;
    int h = hw / WWI, w = hw % WWI;
    const float* xb = g_xd + r * THWSZ;
    const float* ws_[3] = {w1, w2, w3};
    const float* bs_[3] = {b1, b2, b3};
    float total = 0.0f;
#pragma unroll
    for (int m = 0; m < 3; m++) {
        int d = m + 1;
        float cs = bs_[m][r];
        const float* wp = ws_[m] + r * 81;
        for (int kt = 0; kt < 9; kt++) {
            int ti = t + kt - 4;
            if (ti < 0 || ti >= TT) continue;
#pragma unroll
            for (int kh = 0; kh < 3; kh++) {
                int hi = h + (kh - 1) * d;
                if (hi < 0 || hi >= HHH) continue;
#pragma unroll
                for (int kw = 0; kw < 3; kw++) {
                    int wi = w + (kw - 1) * d;
                    if (wi < 0 || wi >= WWI) continue;
                    cs = fmaf(xb[ti * HWSZ + hi * WWI + wi], wp[(kt * 3 + kh) * 3 + kw], cs);
                }
            }
        }
        total = fmaf(wts[m], cs, total);
    }
    g_agg[idx] = total;
}

// ---------------- final: out = feat * (sigmoid(w_back@agg) - 0.5) -----------
__global__ void k_final(float* __restrict__ out, const float* __restrict__ wback) {
    int pos = blockIdx.x * 256 + threadIdx.x;
    if (pos >= THWSZ) return;
    float ag0 = g_agg[pos];
    float ag1 = g_agg[THWSZ + pos];
    float ag2 = g_agg[2 * THWSZ + pos];
    float ag3 = g_agg[3 * THWSZ + pos];
    const float* f = &g_feat[pos * CCH];
    for (int c = 0; c < CCH; c++) {
        float z = wback[c * 4 + 0] * ag0 + wback[c * 4 + 1] * ag1 +
                  wback[c * 4 + 2] * ag2 + wback[c * 4 + 3] * ag3;
        out[c * THWSZ + pos] = f[c] * (sigm(z) - 0.5f);
    }
}

extern "C" void kernel_launch(void* const* d_in, const int* in_sizes, int n_in,
                              void* d_out, int out_size) {
    const float* x       = (const float*)d_in[0];
    const float* w_dc2   = (const float*)d_in[1];
    const float* w_ofs_l = (const float*)d_in[2];
    const float* b_ofs_l = (const float*)d_in[3];
    const float* w_ofs_r = (const float*)d_in[4];
    const float* b_ofs_r = (const float*)d_in[5];
    const float* ca_w1   = (const float*)d_in[6];
    const float* ca_w2   = (const float*)d_in[7];
    const float* w_down  = (const float*)d_in[8];
    const float* sa1_w   = (const float*)d_in[9];
    const float* sa1_b   = (const float*)d_in[10];
    const float* sa2_w   = (const float*)d_in[11];
    const float* sa2_b   = (const float*)d_in[12];
    const float* sa3_w   = (const float*)d_in[13];
    const float* sa3_b   = (const float*)d_in[14];
    const float* weights = (const float*)d_in[15];
    const float* weights2= (const float*)d_in[16];
    const float* w_back  = (const float*)d_in[17];
    float* out = (float*)d_out;

    k_x2<<<THWSZ / 64, 256>>>(x, w_dc2);
    k_off<<<(2 * TT * 2 * SS + 255) / 256, 256>>>(x, w_ofs_l, b_ofs_l, w_ofs_r, b_ofs_r);
    k_sample<<<(2 * TT * SS + 255) / 256, 256>>>();

    for (int br = 0; br < 2; br++) {
        dim3 g1(HWSZ / 64, SS / 64, TT);
        k_gemm1<<<g1, 256>>>(x, br);
        dim3 gs(HWSZ / 256, TT);
        k_stats<<<gs, 256>>>();
        k_y<<<(TT * HWSZ + 255) / 256, 256>>>(ca_w1, ca_w2);
        dim3 g2(HWSZ / 64, 1, TT);
        k_gemm2<<<g2, 256>>>(br, weights2, br);
    }

    k_xd<<<(RCC * THWSZ + 255) / 256, 256>>>(x, w_down);
    k_agg<<<(RCC * THWSZ + 255) / 256, 256>>>(sa1_w, sa1_b, sa2_w, sa2_b, sa3_w, sa3_b, weights);
    k_final<<<(THWSZ + 255) / 256, 256>>>(out, w_back);
}